// round 1
// baseline (speedup 1.0000x reference)
#include <cuda_runtime.h>
#include <math.h>

#define NODES 30000
#define EDGES 400000

// ------------------------- device scratch (static, no allocs) -------------
__device__ __align__(16) float g_fs [NODES * 256];
__device__ __align__(16) float g_fd [NODES * 256];
__device__ __align__(16) float g_res[NODES * 256];
__device__ __align__(16) float g_h1 [NODES * 256];
__device__ __align__(16) float g_h2 [NODES * 256];
__device__ __align__(16) float g_h3 [NODES * 160];
__device__ int   g_deg[NODES];
__device__ int   g_off[NODES + 1];
__device__ int   g_cur[NODES];
__device__ int   g_srcs[EDGES];
__device__ float g_sum[256], g_sq[256], g_scale[256], g_shift[256];

// ------------------------- small utility kernels --------------------------
__global__ void zero_int_kernel(int* p, int n) {
    int i = blockIdx.x * blockDim.x + threadIdx.x;
    if (i < n) p[i] = 0;
}

__global__ void zero_bn_kernel(float* s, float* q) {
    int i = threadIdx.x;  // 256 threads
    s[i] = 0.f; q[i] = 0.f;
}

__global__ void count_deg_kernel(const int* __restrict__ dst, int* deg, int e_cnt) {
    int e = blockIdx.x * blockDim.x + threadIdx.x;
    if (e < e_cnt) atomicAdd(&deg[dst[e]], 1);
}

__global__ void copy_int_kernel(const int* a, int* b, int n) {
    int i = blockIdx.x * blockDim.x + threadIdx.x;
    if (i < n) b[i] = a[i];
}

__global__ void scatter_kernel(const int* __restrict__ src, const int* __restrict__ dst,
                               int* cur, int* srcs, int e_cnt) {
    int e = blockIdx.x * blockDim.x + threadIdx.x;
    if (e < e_cnt) {
        int pos = atomicAdd(&cur[dst[e]], 1);
        srcs[pos] = src[e];
    }
}

// single-block inclusive scan over NODES entries -> exclusive offsets
__global__ void scan_kernel(const int* __restrict__ deg, int* off, int n) {
    __shared__ int sh[1024];
    __shared__ int carrySh;
    int tid = threadIdx.x;
    if (tid == 0) { off[0] = 0; carrySh = 0; }
    __syncthreads();
    for (int base = 0; base < n; base += 1024) {
        int i = base + tid;
        int v = (i < n) ? deg[i] : 0;
        sh[tid] = v;
        __syncthreads();
        for (int d = 1; d < 1024; d <<= 1) {
            int t = (tid >= d) ? sh[tid - d] : 0;
            __syncthreads();
            sh[tid] += t;
            __syncthreads();
        }
        int carry = carrySh;
        if (i < n) off[i + 1] = carry + sh[tid];
        __syncthreads();
        if (tid == 1023) carrySh = carry + sh[1023];
        __syncthreads();
    }
}

// ------------------------- SGEMM: C[M,N] = A[M,K] @ B[K,N] ----------------
// BM=BN=128, BK=16, 256 threads, 8x8 per thread (split 4+4 rows/cols).
__global__ __launch_bounds__(256) void sgemm_kernel(
    const float* __restrict__ A, const float* __restrict__ B,
    float* __restrict__ C, int M, int N, int K)
{
    __shared__ float As[16][128];
    __shared__ float Bs[16][128];

    const int tid = threadIdx.x;
    const int ty = tid >> 4;        // 0..15
    const int tx = tid & 15;        // 0..15
    const int m0 = blockIdx.y * 128;
    const int n0 = blockIdx.x * 128;

    // A-load mapping: row = tid/2 (0..127), kq = (tid&1)*8 -> 2 float4s
    const int a_row = tid >> 1;
    const int a_kq  = (tid & 1) * 8;
    // B-load mapping: krow = tid/16 (0..15), nq = (tid%16)*8 -> 2 float4s
    const int b_kr = tid >> 4;
    const int b_nq = (tid & 15) * 8;

    float acc[8][8];
#pragma unroll
    for (int i = 0; i < 8; i++)
#pragma unroll
        for (int j = 0; j < 8; j++) acc[i][j] = 0.f;

    for (int k0 = 0; k0 < K; k0 += 16) {
        // load A tile
        {
            int row = m0 + a_row;
            if (row < M) {
                const float4 v0 = *(const float4*)(A + (size_t)row * K + k0 + a_kq);
                const float4 v1 = *(const float4*)(A + (size_t)row * K + k0 + a_kq + 4);
                As[a_kq + 0][a_row] = v0.x; As[a_kq + 1][a_row] = v0.y;
                As[a_kq + 2][a_row] = v0.z; As[a_kq + 3][a_row] = v0.w;
                As[a_kq + 4][a_row] = v1.x; As[a_kq + 5][a_row] = v1.y;
                As[a_kq + 6][a_row] = v1.z; As[a_kq + 7][a_row] = v1.w;
            } else {
#pragma unroll
                for (int i = 0; i < 8; i++) As[a_kq + i][a_row] = 0.f;
            }
        }
        // load B tile
        {
            int col = n0 + b_nq;
            const float* bp = B + (size_t)(k0 + b_kr) * N + col;
            if (col + 7 < N) {
                const float4 v0 = *(const float4*)(bp);
                const float4 v1 = *(const float4*)(bp + 4);
                *(float4*)&Bs[b_kr][b_nq]     = v0;
                *(float4*)&Bs[b_kr][b_nq + 4] = v1;
            } else {
#pragma unroll
                for (int i = 0; i < 8; i++)
                    Bs[b_kr][b_nq + i] = (col + i < N) ? bp[i] : 0.f;
            }
        }
        __syncthreads();

#pragma unroll
        for (int kk = 0; kk < 16; kk++) {
            float a[8], b[8];
#pragma unroll
            for (int i = 0; i < 4; i++) {
                a[i]     = As[kk][ty * 4 + i];
                a[4 + i] = As[kk][ty * 4 + 64 + i];
                b[i]     = Bs[kk][tx * 4 + i];
                b[4 + i] = Bs[kk][tx * 4 + 64 + i];
            }
#pragma unroll
            for (int i = 0; i < 8; i++)
#pragma unroll
                for (int j = 0; j < 8; j++)
                    acc[i][j] = fmaf(a[i], b[j], acc[i][j]);
        }
        __syncthreads();
    }

#pragma unroll
    for (int i = 0; i < 8; i++) {
        int r = m0 + ((i < 4) ? (ty * 4 + i) : (64 + ty * 4 + i - 4));
        if (r >= M) continue;
#pragma unroll
        for (int j = 0; j < 8; j++) {
            int c = n0 + ((j < 4) ? (tx * 4 + j) : (64 + tx * 4 + j - 4));
            if (c < N) C[(size_t)r * N + c] = acc[i][j];
        }
    }
}

// ------------------------- GATv2 edge kernel ------------------------------
// One warp per destination node; online softmax over incoming edges.
// F = J*32 flattened features, OUTD = per-head dim (64 or 40).
template <int J, int OUTD, bool RELU>
__global__ __launch_bounds__(256) void gat_edge_kernel(
    const float* __restrict__ fs, const float* __restrict__ fd,
    const float* __restrict__ res, const float* __restrict__ bias,
    const float* __restrict__ attn,
    const int* __restrict__ off, const int* __restrict__ srcs,
    float* __restrict__ out, int n_nodes)
{
    const int F = J * 32;
    int v = (blockIdx.x * blockDim.x + threadIdx.x) >> 5;
    int lane = threadIdx.x & 31;
    if (v >= n_nodes) return;

    float fdv[J], resv[J], attnr[J], biasr[J], acc[J];
    int hj[J];
#pragma unroll
    for (int j = 0; j < J; j++) {
        int idx = lane + 32 * j;
        fdv[j]   = fd[(size_t)v * F + idx];
        resv[j]  = res[(size_t)v * F + idx];
        attnr[j] = attn[idx];
        biasr[j] = bias[idx];
        acc[j]   = 0.f;
        hj[j]    = idx / OUTD;
    }

    float m0 = -INFINITY, m1 = -INFINITY, m2 = -INFINITY, m3 = -INFINITY;
    float s0 = 0.f, s1 = 0.f, s2 = 0.f, s3 = 0.f;

    int e0 = off[v], e1 = off[v + 1];
    for (int e = e0; e < e1; e++) {
        int u = srcs[e];
        float fsu[J];
        float p0 = 0.f, p1 = 0.f, p2 = 0.f, p3 = 0.f;
#pragma unroll
        for (int j = 0; j < J; j++) {
            fsu[j] = fs[(size_t)u * F + lane + 32 * j];
            float t = fsu[j] + fdv[j];
            float lr = t > 0.f ? t : 0.2f * t;
            float val = attnr[j] * lr;
            p0 += (hj[j] == 0) ? val : 0.f;
            p1 += (hj[j] == 1) ? val : 0.f;
            p2 += (hj[j] == 2) ? val : 0.f;
            p3 += (hj[j] == 3) ? val : 0.f;
        }
#pragma unroll
        for (int o = 16; o > 0; o >>= 1) {
            p0 += __shfl_xor_sync(0xffffffffu, p0, o);
            p1 += __shfl_xor_sync(0xffffffffu, p1, o);
            p2 += __shfl_xor_sync(0xffffffffu, p2, o);
            p3 += __shfl_xor_sync(0xffffffffu, p3, o);
        }
        // online softmax update per head
        float n0v = fmaxf(m0, p0), n1v = fmaxf(m1, p1);
        float n2v = fmaxf(m2, p2), n3v = fmaxf(m3, p3);
        float sc0 = __expf(m0 - n0v), sc1 = __expf(m1 - n1v);
        float sc2 = __expf(m2 - n2v), sc3 = __expf(m3 - n3v);
        float w0 = __expf(p0 - n0v), w1 = __expf(p1 - n1v);
        float w2 = __expf(p2 - n2v), w3 = __expf(p3 - n3v);
        s0 = s0 * sc0 + w0; s1 = s1 * sc1 + w1;
        s2 = s2 * sc2 + w2; s3 = s3 * sc3 + w3;
        m0 = n0v; m1 = n1v; m2 = n2v; m3 = n3v;
#pragma unroll
        for (int j = 0; j < J; j++) {
            float sc = hj[j] == 0 ? sc0 : hj[j] == 1 ? sc1 : hj[j] == 2 ? sc2 : sc3;
            float w  = hj[j] == 0 ? w0  : hj[j] == 1 ? w1  : hj[j] == 2 ? w2  : w3;
            acc[j] = acc[j] * sc + w * fsu[j];
        }
    }

    float r0 = 1.f / fmaxf(s0, 1e-9f), r1 = 1.f / fmaxf(s1, 1e-9f);
    float r2 = 1.f / fmaxf(s2, 1e-9f), r3 = 1.f / fmaxf(s3, 1e-9f);
#pragma unroll
    for (int j = 0; j < J; j++) {
        float rr = hj[j] == 0 ? r0 : hj[j] == 1 ? r1 : hj[j] == 2 ? r2 : r3;
        float o = acc[j] * rr + resv[j] + biasr[j];
        if (RELU) o = fmaxf(o, 0.f);
        out[(size_t)v * F + lane + 32 * j] = o;
    }
}

// ------------------------- batchnorm ---------------------------------------
__global__ void bn_stats_kernel(const float* __restrict__ x, float* sums, float* sqs, int n) {
    int f = threadIdx.x;  // 256 threads
    float s = 0.f, q = 0.f;
    for (int r = blockIdx.x; r < n; r += gridDim.x) {
        float v = x[(size_t)r * 256 + f];
        s += v; q += v * v;
    }
    atomicAdd(&sums[f], s);
    atomicAdd(&sqs[f], q);
}

__global__ void bn_finalize_kernel(const float* sums, const float* sqs,
                                   const float* __restrict__ g, const float* __restrict__ be,
                                   float* scale, float* shift, int n) {
    int f = threadIdx.x;
    float mean = sums[f] / (float)n;
    float var  = sqs[f] / (float)n - mean * mean;
    float sc = g[f] * rsqrtf(var + 1e-5f);
    scale[f] = sc;
    shift[f] = be[f] - mean * sc;
}

__global__ void bn_apply_relu_kernel(float* x, const float* __restrict__ scale,
                                     const float* __restrict__ shift, int total) {
    int i = blockIdx.x * blockDim.x + threadIdx.x;
    if (i < total) {
        int f = i & 255;
        x[i] = fmaxf(fmaf(x[i], scale[f], shift[f]), 0.f);
    }
}

// ------------------------- head-mean + log_softmax ------------------------
__global__ void head_mean_logsoftmax_kernel(const float* __restrict__ h,
                                            float* __restrict__ out, int n_nodes) {
    int v = (blockIdx.x * blockDim.x + threadIdx.x) >> 5;
    int lane = threadIdx.x & 31;
    if (v >= n_nodes) return;
    const float* row = h + (size_t)v * 160;

    int c1 = lane;               // 0..31
    int c2 = 32 + lane;          // valid for lane<8
    float v1 = 0.25f * (row[c1] + row[40 + c1] + row[80 + c1] + row[120 + c1]);
    float v2 = -INFINITY;
    if (lane < 8) v2 = 0.25f * (row[c2] + row[40 + c2] + row[80 + c2] + row[120 + c2]);

    float mx = fmaxf(v1, v2);
#pragma unroll
    for (int o = 16; o > 0; o >>= 1) mx = fmaxf(mx, __shfl_xor_sync(0xffffffffu, mx, o));

    float e = expf(v1 - mx) + (lane < 8 ? expf(v2 - mx) : 0.f);
#pragma unroll
    for (int o = 16; o > 0; o >>= 1) e += __shfl_xor_sync(0xffffffffu, e, o);

    float lse = mx + logf(e);
    out[(size_t)v * 40 + c1] = v1 - lse;
    if (lane < 8) out[(size_t)v * 40 + c2] = v2 - lse;
}

// ------------------------- host orchestration ------------------------------
static inline void launch_sgemm(const float* A, const float* B, float* C,
                                int M, int N, int K) {
    dim3 grid((N + 127) / 128, (M + 127) / 128);
    sgemm_kernel<<<grid, 256>>>(A, B, C, M, N, K);
}

extern "C" void kernel_launch(void* const* d_in, const int* in_sizes, int n_in,
                              void* d_out, int out_size) {
    const float* x      = (const float*)d_in[0];
    const int*   src    = (const int*)d_in[1];
    const int*   dst    = (const int*)d_in[2];
    const float* Wsrc0  = (const float*)d_in[3];
    const float* Wdst0  = (const float*)d_in[4];
    const float* b0     = (const float*)d_in[5];
    const float* attn0  = (const float*)d_in[6];
    const float* resW0  = (const float*)d_in[7];
    const float* Wsrc1  = (const float*)d_in[8];
    const float* Wdst1  = (const float*)d_in[9];
    const float* b1     = (const float*)d_in[10];
    const float* attn1  = (const float*)d_in[11];
    const float* Wsrc2  = (const float*)d_in[12];
    const float* Wdst2  = (const float*)d_in[13];
    const float* b2     = (const float*)d_in[14];
    const float* attn2  = (const float*)d_in[15];
    const float* resW2  = (const float*)d_in[16];
    const float* g0     = (const float*)d_in[17];
    const float* be0    = (const float*)d_in[18];
    const float* g1     = (const float*)d_in[19];
    const float* be1    = (const float*)d_in[20];
    float* out = (float*)d_out;

    const int NN = in_sizes[0] / 128;   // 30000
    const int EE = in_sizes[1];         // 400000

    float *fs, *fd, *res, *h1, *h2, *h3;
    int *deg, *off, *cur, *srcs;
    float *bsum, *bsq, *bscale, *bshift;
    cudaGetSymbolAddress((void**)&fs,  g_fs);
    cudaGetSymbolAddress((void**)&fd,  g_fd);
    cudaGetSymbolAddress((void**)&res, g_res);
    cudaGetSymbolAddress((void**)&h1,  g_h1);
    cudaGetSymbolAddress((void**)&h2,  g_h2);
    cudaGetSymbolAddress((void**)&h3,  g_h3);
    cudaGetSymbolAddress((void**)&deg, g_deg);
    cudaGetSymbolAddress((void**)&off, g_off);
    cudaGetSymbolAddress((void**)&cur, g_cur);
    cudaGetSymbolAddress((void**)&srcs, g_srcs);
    cudaGetSymbolAddress((void**)&bsum, g_sum);
    cudaGetSymbolAddress((void**)&bsq,  g_sq);
    cudaGetSymbolAddress((void**)&bscale, g_scale);
    cudaGetSymbolAddress((void**)&bshift, g_shift);

    const int TB = 256;
    const int nodeBlocks = (NN + TB - 1) / TB;
    const int edgeBlocks = (EE + TB - 1) / TB;
    const int warpNodeBlocks = (NN * 32 + TB - 1) / TB;

    // ---- build dst-CSR ----
    zero_int_kernel<<<nodeBlocks, TB>>>(deg, NN);
    count_deg_kernel<<<edgeBlocks, TB>>>(dst, deg, EE);
    scan_kernel<<<1, 1024>>>(deg, off, NN);
    copy_int_kernel<<<nodeBlocks, TB>>>(off, cur, NN);
    scatter_kernel<<<edgeBlocks, TB>>>(src, dst, cur, srcs, EE);

    // ---- layer 0: 128 -> 4x64, projected residual, relu ----
    launch_sgemm(x, Wsrc0, fs,  NN, 256, 128);
    launch_sgemm(x, Wdst0, fd,  NN, 256, 128);
    launch_sgemm(x, resW0, res, NN, 256, 128);
    gat_edge_kernel<8, 64, true><<<warpNodeBlocks, TB>>>(fs, fd, res, b0, attn0, off, srcs, h1, NN);

    // BN0 + relu (in place)
    zero_bn_kernel<<<1, 256>>>(bsum, bsq);
    bn_stats_kernel<<<128, 256>>>(h1, bsum, bsq, NN);
    bn_finalize_kernel<<<1, 256>>>(bsum, bsq, g0, be0, bscale, bshift, NN);
    bn_apply_relu_kernel<<<(NN * 256 + TB - 1) / TB, TB>>>(h1, bscale, bshift, NN * 256);

    // ---- layer 1: 256 -> 4x64, identity residual, relu ----
    launch_sgemm(h1, Wsrc1, fs, NN, 256, 256);
    launch_sgemm(h1, Wdst1, fd, NN, 256, 256);
    gat_edge_kernel<8, 64, true><<<warpNodeBlocks, TB>>>(fs, fd, h1, b1, attn1, off, srcs, h2, NN);

    // BN1 + relu (in place)
    zero_bn_kernel<<<1, 256>>>(bsum, bsq);
    bn_stats_kernel<<<128, 256>>>(h2, bsum, bsq, NN);
    bn_finalize_kernel<<<1, 256>>>(bsum, bsq, g1, be1, bscale, bshift, NN);
    bn_apply_relu_kernel<<<(NN * 256 + TB - 1) / TB, TB>>>(h2, bscale, bshift, NN * 256);

    // ---- layer 2: 256 -> 4x40, projected residual, no relu ----
    launch_sgemm(h2, Wsrc2, fs,  NN, 160, 256);
    launch_sgemm(h2, Wdst2, fd,  NN, 160, 256);
    launch_sgemm(h2, resW2, res, NN, 160, 256);
    gat_edge_kernel<5, 40, false><<<warpNodeBlocks, TB>>>(fs, fd, res, b2, attn2, off, srcs, h3, NN);

    // ---- head mean + log_softmax ----
    head_mean_logsoftmax_kernel<<<warpNodeBlocks, TB>>>(h3, out, NN);

    (void)n_in; (void)out_size;
}

// round 2
// speedup vs baseline: 1.6509x; 1.6509x over previous
#include <cuda_runtime.h>
#include <math.h>
#include <stdint.h>

#define NODES 30000
#define EDGES 400000

// ------------------------- device scratch (static, no allocs) -------------
__device__ __align__(16) float g_fs [NODES * 256];
__device__ __align__(16) float g_fd [NODES * 256];
__device__ __align__(16) float g_res[NODES * 256];
__device__ __align__(16) float g_h1 [NODES * 256];
__device__ __align__(16) float g_h2 [NODES * 256];
__device__ __align__(16) float g_h3 [NODES * 160];
__device__ int   g_deg[NODES];
__device__ int   g_off[NODES + 1];
__device__ int   g_cur[NODES];
__device__ int   g_srcs[EDGES];
__device__ float g_sum[256], g_sq[256], g_scale[256], g_shift[256];

// ------------------------- small utility kernels --------------------------
__global__ void zero_int_kernel(int* p, int n) {
    int i = blockIdx.x * blockDim.x + threadIdx.x;
    if (i < n) p[i] = 0;
}

__global__ void zero_bn_kernel(float* s, float* q) {
    int i = threadIdx.x;  // 256 threads
    s[i] = 0.f; q[i] = 0.f;
}

__global__ void count_deg_kernel(const int* __restrict__ dst, int* deg, int e_cnt) {
    int e = blockIdx.x * blockDim.x + threadIdx.x;
    if (e < e_cnt) atomicAdd(&deg[dst[e]], 1);
}

__global__ void copy_int_kernel(const int* a, int* b, int n) {
    int i = blockIdx.x * blockDim.x + threadIdx.x;
    if (i < n) b[i] = a[i];
}

__global__ void scatter_kernel(const int* __restrict__ src, const int* __restrict__ dst,
                               int* cur, int* srcs, int e_cnt) {
    int e = blockIdx.x * blockDim.x + threadIdx.x;
    if (e < e_cnt) {
        int pos = atomicAdd(&cur[dst[e]], 1);
        srcs[pos] = src[e];
    }
}

// single-block inclusive scan over NODES entries -> exclusive offsets
__global__ void scan_kernel(const int* __restrict__ deg, int* off, int n) {
    __shared__ int sh[1024];
    __shared__ int carrySh;
    int tid = threadIdx.x;
    if (tid == 0) { off[0] = 0; carrySh = 0; }
    __syncthreads();
    for (int base = 0; base < n; base += 1024) {
        int i = base + tid;
        int v = (i < n) ? deg[i] : 0;
        sh[tid] = v;
        __syncthreads();
        for (int d = 1; d < 1024; d <<= 1) {
            int t = (tid >= d) ? sh[tid - d] : 0;
            __syncthreads();
            sh[tid] += t;
            __syncthreads();
        }
        int carry = carrySh;
        if (i < n) off[i + 1] = carry + sh[tid];
        __syncthreads();
        if (tid == 1023) carrySh = carry + sh[1023];
        __syncthreads();
    }
}

// ------------------------- TF32 tensor-core GEMM ---------------------------
// C[M,N] = A[M,K] @ B[K,N]. BM=128, BN=64, BK=32. 128 threads = 4 warps in a
// 2(M) x 2(N) grid; warp tile 64x32 via mma.sync.m16n8k8.tf32 (fp32 accum).
// Smem layouts chosen for zero bank conflicts on both store and frag-load:
//   As[m][k]: stride 36  -> store banks 4*seg+row, frag banks 4g+tg (distinct)
//   Bs[k][n]: stride 72  -> store banks 4*nseg,     frag banks 8tg+g (distinct)
__device__ __forceinline__ uint32_t f32_to_tf32(float x) {
    uint32_t r;
    asm("cvt.rna.tf32.f32 %0, %1;" : "=r"(r) : "f"(x));
    return r;
}

__global__ __launch_bounds__(128) void tf32_gemm_kernel(
    const float* __restrict__ A, const float* __restrict__ B,
    float* __restrict__ C, int M, int N, int K)
{
    __shared__ float As[128][36];
    __shared__ float Bs[32][72];

    const int tid  = threadIdx.x;
    const int lane = tid & 31;
    const int wid  = tid >> 5;
    const int warpM = wid & 1;      // 0..1
    const int warpN = wid >> 1;     // 0..1
    const int g  = lane >> 2;       // 0..7
    const int tg = lane & 3;        // 0..3

    const int m0 = blockIdx.y * 128;
    const int n0 = blockIdx.x * 64;

    // A loader mapping: seg = tid%8 (float4 along k), row0 = tid/8 (0..15)
    const int a_seg  = tid & 7;
    const int a_row0 = tid >> 3;
    // B loader mapping: kr0 = tid/16 (0..7), nseg = tid%16 (float4 along n)
    const int b_kr0  = tid >> 4;
    const int b_nseg = tid & 15;
    const int b_col  = n0 + b_nseg * 4;
    const bool b_ok  = (b_col < N);

    float acc[4][4][4];
#pragma unroll
    for (int i = 0; i < 4; i++)
#pragma unroll
        for (int j = 0; j < 4; j++)
#pragma unroll
            for (int k = 0; k < 4; k++) acc[i][j][k] = 0.f;

    for (int kt = 0; kt < K; kt += 32) {
        // ---- load A tile 128x32 (8 float4 per thread), cvt to tf32 ----
#pragma unroll
        for (int it = 0; it < 8; it++) {
            int row = a_row0 + 16 * it;
            int grow = m0 + row;
            float4 v;
            if (grow < M) {
                v = *(const float4*)(A + (size_t)grow * K + kt + a_seg * 4);
            } else {
                v = make_float4(0.f, 0.f, 0.f, 0.f);
            }
            float4 t;
            t.x = __uint_as_float(f32_to_tf32(v.x));
            t.y = __uint_as_float(f32_to_tf32(v.y));
            t.z = __uint_as_float(f32_to_tf32(v.z));
            t.w = __uint_as_float(f32_to_tf32(v.w));
            *(float4*)&As[row][a_seg * 4] = t;
        }
        // ---- load B tile 32x64 (4 float4 per thread), cvt to tf32 ----
#pragma unroll
        for (int it = 0; it < 4; it++) {
            int kr = b_kr0 + 8 * it;
            float4 v;
            if (b_ok) {
                v = *(const float4*)(B + (size_t)(kt + kr) * N + b_col);
            } else {
                v = make_float4(0.f, 0.f, 0.f, 0.f);
            }
            float4 t;
            t.x = __uint_as_float(f32_to_tf32(v.x));
            t.y = __uint_as_float(f32_to_tf32(v.y));
            t.z = __uint_as_float(f32_to_tf32(v.z));
            t.w = __uint_as_float(f32_to_tf32(v.w));
            *(float4*)&Bs[kr][b_nseg * 4] = t;
        }
        __syncthreads();

#pragma unroll
        for (int ks = 0; ks < 4; ks++) {
            const int kk = ks * 8;
            uint32_t af[4][4];
#pragma unroll
            for (int mt = 0; mt < 4; mt++) {
                int mr = warpM * 64 + mt * 16 + g;
                af[mt][0] = __float_as_uint(As[mr    ][kk + tg]);
                af[mt][1] = __float_as_uint(As[mr + 8][kk + tg]);
                af[mt][2] = __float_as_uint(As[mr    ][kk + tg + 4]);
                af[mt][3] = __float_as_uint(As[mr + 8][kk + tg + 4]);
            }
            uint32_t bf[4][2];
#pragma unroll
            for (int nt = 0; nt < 4; nt++) {
                int nc = warpN * 32 + nt * 8 + g;
                bf[nt][0] = __float_as_uint(Bs[kk + tg    ][nc]);
                bf[nt][1] = __float_as_uint(Bs[kk + tg + 4][nc]);
            }
#pragma unroll
            for (int mt = 0; mt < 4; mt++)
#pragma unroll
                for (int nt = 0; nt < 4; nt++) {
                    asm volatile(
                        "mma.sync.aligned.m16n8k8.row.col.f32.tf32.tf32.f32 "
                        "{%0,%1,%2,%3}, {%4,%5,%6,%7}, {%8,%9}, {%0,%1,%2,%3};"
                        : "+f"(acc[mt][nt][0]), "+f"(acc[mt][nt][1]),
                          "+f"(acc[mt][nt][2]), "+f"(acc[mt][nt][3])
                        : "r"(af[mt][0]), "r"(af[mt][1]),
                          "r"(af[mt][2]), "r"(af[mt][3]),
                          "r"(bf[nt][0]), "r"(bf[nt][1]));
                }
        }
        __syncthreads();
    }

    // ---- epilogue ----
#pragma unroll
    for (int mt = 0; mt < 4; mt++) {
        int r0 = m0 + warpM * 64 + mt * 16 + g;
#pragma unroll
        for (int nt = 0; nt < 4; nt++) {
            int cc = n0 + warpN * 32 + nt * 8 + 2 * tg;
            if (cc < N) {
                if (r0 < M) {
                    float2 v = make_float2(acc[mt][nt][0], acc[mt][nt][1]);
                    *(float2*)(C + (size_t)r0 * N + cc) = v;
                }
                if (r0 + 8 < M) {
                    float2 v = make_float2(acc[mt][nt][2], acc[mt][nt][3]);
                    *(float2*)(C + (size_t)(r0 + 8) * N + cc) = v;
                }
            }
        }
    }
}

// ------------------------- GATv2 edge kernel ------------------------------
// One warp per destination node; online softmax over incoming edges.
// F = J*32 flattened features, OUTD = per-head dim (64 or 40).
template <int J, int OUTD, bool RELU>
__global__ __launch_bounds__(256) void gat_edge_kernel(
    const float* __restrict__ fs, const float* __restrict__ fd,
    const float* __restrict__ res, const float* __restrict__ bias,
    const float* __restrict__ attn,
    const int* __restrict__ off, const int* __restrict__ srcs,
    float* __restrict__ out, int n_nodes)
{
    const int F = J * 32;
    int v = (blockIdx.x * blockDim.x + threadIdx.x) >> 5;
    int lane = threadIdx.x & 31;
    if (v >= n_nodes) return;

    float fdv[J], resv[J], attnr[J], biasr[J], acc[J];
    int hj[J];
#pragma unroll
    for (int j = 0; j < J; j++) {
        int idx = lane + 32 * j;
        fdv[j]   = fd[(size_t)v * F + idx];
        resv[j]  = res[(size_t)v * F + idx];
        attnr[j] = attn[idx];
        biasr[j] = bias[idx];
        acc[j]   = 0.f;
        hj[j]    = idx / OUTD;
    }

    float m0 = -INFINITY, m1 = -INFINITY, m2 = -INFINITY, m3 = -INFINITY;
    float s0 = 0.f, s1 = 0.f, s2 = 0.f, s3 = 0.f;

    int e0 = off[v], e1 = off[v + 1];
    for (int e = e0; e < e1; e++) {
        int u = srcs[e];
        float fsu[J];
        float p0 = 0.f, p1 = 0.f, p2 = 0.f, p3 = 0.f;
#pragma unroll
        for (int j = 0; j < J; j++) {
            fsu[j] = fs[(size_t)u * F + lane + 32 * j];
            float t = fsu[j] + fdv[j];
            float lr = t > 0.f ? t : 0.2f * t;
            float val = attnr[j] * lr;
            p0 += (hj[j] == 0) ? val : 0.f;
            p1 += (hj[j] == 1) ? val : 0.f;
            p2 += (hj[j] == 2) ? val : 0.f;
            p3 += (hj[j] == 3) ? val : 0.f;
        }
#pragma unroll
        for (int o = 16; o > 0; o >>= 1) {
            p0 += __shfl_xor_sync(0xffffffffu, p0, o);
            p1 += __shfl_xor_sync(0xffffffffu, p1, o);
            p2 += __shfl_xor_sync(0xffffffffu, p2, o);
            p3 += __shfl_xor_sync(0xffffffffu, p3, o);
        }
        // online softmax update per head
        float n0v = fmaxf(m0, p0), n1v = fmaxf(m1, p1);
        float n2v = fmaxf(m2, p2), n3v = fmaxf(m3, p3);
        float sc0 = __expf(m0 - n0v), sc1 = __expf(m1 - n1v);
        float sc2 = __expf(m2 - n2v), sc3 = __expf(m3 - n3v);
        float w0 = __expf(p0 - n0v), w1 = __expf(p1 - n1v);
        float w2 = __expf(p2 - n2v), w3 = __expf(p3 - n3v);
        s0 = s0 * sc0 + w0; s1 = s1 * sc1 + w1;
        s2 = s2 * sc2 + w2; s3 = s3 * sc3 + w3;
        m0 = n0v; m1 = n1v; m2 = n2v; m3 = n3v;
#pragma unroll
        for (int j = 0; j < J; j++) {
            float sc = hj[j] == 0 ? sc0 : hj[j] == 1 ? sc1 : hj[j] == 2 ? sc2 : sc3;
            float w  = hj[j] == 0 ? w0  : hj[j] == 1 ? w1  : hj[j] == 2 ? w2  : w3;
            acc[j] = acc[j] * sc + w * fsu[j];
        }
    }

    float r0 = 1.f / fmaxf(s0, 1e-9f), r1 = 1.f / fmaxf(s1, 1e-9f);
    float r2 = 1.f / fmaxf(s2, 1e-9f), r3 = 1.f / fmaxf(s3, 1e-9f);
#pragma unroll
    for (int j = 0; j < J; j++) {
        float rr = hj[j] == 0 ? r0 : hj[j] == 1 ? r1 : hj[j] == 2 ? r2 : r3;
        float o = acc[j] * rr + resv[j] + biasr[j];
        if (RELU) o = fmaxf(o, 0.f);
        out[(size_t)v * F + lane + 32 * j] = o;
    }
}

// ------------------------- batchnorm ---------------------------------------
__global__ void bn_stats_kernel(const float* __restrict__ x, float* sums, float* sqs, int n) {
    int f = threadIdx.x;  // 256 threads
    float s = 0.f, q = 0.f;
    for (int r = blockIdx.x; r < n; r += gridDim.x) {
        float v = x[(size_t)r * 256 + f];
        s += v; q += v * v;
    }
    atomicAdd(&sums[f], s);
    atomicAdd(&sqs[f], q);
}

__global__ void bn_finalize_kernel(const float* sums, const float* sqs,
                                   const float* __restrict__ g, const float* __restrict__ be,
                                   float* scale, float* shift, int n) {
    int f = threadIdx.x;
    float mean = sums[f] / (float)n;
    float var  = sqs[f] / (float)n - mean * mean;
    float sc = g[f] * rsqrtf(var + 1e-5f);
    scale[f] = sc;
    shift[f] = be[f] - mean * sc;
}

__global__ void bn_apply_relu_kernel(float* x, const float* __restrict__ scale,
                                     const float* __restrict__ shift, int total) {
    int i = blockIdx.x * blockDim.x + threadIdx.x;
    if (i < total) {
        int f = i & 255;
        x[i] = fmaxf(fmaf(x[i], scale[f], shift[f]), 0.f);
    }
}

// ------------------------- head-mean + log_softmax ------------------------
__global__ void head_mean_logsoftmax_kernel(const float* __restrict__ h,
                                            float* __restrict__ out, int n_nodes) {
    int v = (blockIdx.x * blockDim.x + threadIdx.x) >> 5;
    int lane = threadIdx.x & 31;
    if (v >= n_nodes) return;
    const float* row = h + (size_t)v * 160;

    int c1 = lane;               // 0..31
    int c2 = 32 + lane;          // valid for lane<8
    float v1 = 0.25f * (row[c1] + row[40 + c1] + row[80 + c1] + row[120 + c1]);
    float v2 = -INFINITY;
    if (lane < 8) v2 = 0.25f * (row[c2] + row[40 + c2] + row[80 + c2] + row[120 + c2]);

    float mx = fmaxf(v1, v2);
#pragma unroll
    for (int o = 16; o > 0; o >>= 1) mx = fmaxf(mx, __shfl_xor_sync(0xffffffffu, mx, o));

    float e = expf(v1 - mx) + (lane < 8 ? expf(v2 - mx) : 0.f);
#pragma unroll
    for (int o = 16; o > 0; o >>= 1) e += __shfl_xor_sync(0xffffffffu, e, o);

    float lse = mx + logf(e);
    out[(size_t)v * 40 + c1] = v1 - lse;
    if (lane < 8) out[(size_t)v * 40 + c2] = v2 - lse;
}

// ------------------------- host orchestration ------------------------------
static inline void launch_gemm(const float* A, const float* B, float* C,
                               int M, int N, int K) {
    dim3 grid((N + 63) / 64, (M + 127) / 128);
    tf32_gemm_kernel<<<grid, 128>>>(A, B, C, M, N, K);
}

extern "C" void kernel_launch(void* const* d_in, const int* in_sizes, int n_in,
                              void* d_out, int out_size) {
    const float* x      = (const float*)d_in[0];
    const int*   src    = (const int*)d_in[1];
    const int*   dst    = (const int*)d_in[2];
    const float* Wsrc0  = (const float*)d_in[3];
    const float* Wdst0  = (const float*)d_in[4];
    const float* b0     = (const float*)d_in[5];
    const float* attn0  = (const float*)d_in[6];
    const float* resW0  = (const float*)d_in[7];
    const float* Wsrc1  = (const float*)d_in[8];
    const float* Wdst1  = (const float*)d_in[9];
    const float* b1     = (const float*)d_in[10];
    const float* attn1  = (const float*)d_in[11];
    const float* Wsrc2  = (const float*)d_in[12];
    const float* Wdst2  = (const float*)d_in[13];
    const float* b2     = (const float*)d_in[14];
    const float* attn2  = (const float*)d_in[15];
    const float* resW2  = (const float*)d_in[16];
    const float* g0     = (const float*)d_in[17];
    const float* be0    = (const float*)d_in[18];
    const float* g1     = (const float*)d_in[19];
    const float* be1    = (const float*)d_in[20];
    float* out = (float*)d_out;

    const int NN = in_sizes[0] / 128;   // 30000
    const int EE = in_sizes[1];         // 400000

    float *fs, *fd, *res, *h1, *h2, *h3;
    int *deg, *off, *cur, *srcs;
    float *bsum, *bsq, *bscale, *bshift;
    cudaGetSymbolAddress((void**)&fs,  g_fs);
    cudaGetSymbolAddress((void**)&fd,  g_fd);
    cudaGetSymbolAddress((void**)&res, g_res);
    cudaGetSymbolAddress((void**)&h1,  g_h1);
    cudaGetSymbolAddress((void**)&h2,  g_h2);
    cudaGetSymbolAddress((void**)&h3,  g_h3);
    cudaGetSymbolAddress((void**)&deg, g_deg);
    cudaGetSymbolAddress((void**)&off, g_off);
    cudaGetSymbolAddress((void**)&cur, g_cur);
    cudaGetSymbolAddress((void**)&srcs, g_srcs);
    cudaGetSymbolAddress((void**)&bsum, g_sum);
    cudaGetSymbolAddress((void**)&bsq,  g_sq);
    cudaGetSymbolAddress((void**)&bscale, g_scale);
    cudaGetSymbolAddress((void**)&bshift, g_shift);

    const int TB = 256;
    const int nodeBlocks = (NN + TB - 1) / TB;
    const int edgeBlocks = (EE + TB - 1) / TB;
    const int warpNodeBlocks = (NN * 32 + TB - 1) / TB;

    // ---- build dst-CSR ----
    zero_int_kernel<<<nodeBlocks, TB>>>(deg, NN);
    count_deg_kernel<<<edgeBlocks, TB>>>(dst, deg, EE);
    scan_kernel<<<1, 1024>>>(deg, off, NN);
    copy_int_kernel<<<nodeBlocks, TB>>>(off, cur, NN);
    scatter_kernel<<<edgeBlocks, TB>>>(src, dst, cur, srcs, EE);

    // ---- layer 0: 128 -> 4x64, projected residual, relu ----
    launch_gemm(x, Wsrc0, fs,  NN, 256, 128);
    launch_gemm(x, Wdst0, fd,  NN, 256, 128);
    launch_gemm(x, resW0, res, NN, 256, 128);
    gat_edge_kernel<8, 64, true><<<warpNodeBlocks, TB>>>(fs, fd, res, b0, attn0, off, srcs, h1, NN);

    // BN0 + relu (in place)
    zero_bn_kernel<<<1, 256>>>(bsum, bsq);
    bn_stats_kernel<<<128, 256>>>(h1, bsum, bsq, NN);
    bn_finalize_kernel<<<1, 256>>>(bsum, bsq, g0, be0, bscale, bshift, NN);
    bn_apply_relu_kernel<<<(NN * 256 + TB - 1) / TB, TB>>>(h1, bscale, bshift, NN * 256);

    // ---- layer 1: 256 -> 4x64, identity residual, relu ----
    launch_gemm(h1, Wsrc1, fs, NN, 256, 256);
    launch_gemm(h1, Wdst1, fd, NN, 256, 256);
    gat_edge_kernel<8, 64, true><<<warpNodeBlocks, TB>>>(fs, fd, h1, b1, attn1, off, srcs, h2, NN);

    // BN1 + relu (in place)
    zero_bn_kernel<<<1, 256>>>(bsum, bsq);
    bn_stats_kernel<<<128, 256>>>(h2, bsum, bsq, NN);
    bn_finalize_kernel<<<1, 256>>>(bsum, bsq, g1, be1, bscale, bshift, NN);
    bn_apply_relu_kernel<<<(NN * 256 + TB - 1) / TB, TB>>>(h2, bscale, bshift, NN * 256);

    // ---- layer 2: 256 -> 4x40, projected residual, no relu ----
    launch_gemm(h2, Wsrc2, fs,  NN, 160, 256);
    launch_gemm(h2, Wdst2, fd,  NN, 160, 256);
    launch_gemm(h2, resW2, res, NN, 160, 256);
    gat_edge_kernel<5, 40, false><<<warpNodeBlocks, TB>>>(fs, fd, res, b2, attn2, off, srcs, h3, NN);

    // ---- head mean + log_softmax ----
    head_mean_logsoftmax_kernel<<<warpNodeBlocks, TB>>>(h3, out, NN);

    (void)n_in; (void)out_size;
}